// round 12
// baseline (speedup 1.0000x reference)
#include <cuda_runtime.h>

// AdderNet 2D (K=3,S=1,P=1): out[n,f,y,x] = -sum_{c,i,j} |W[f,c,i,j] - xpad[n,c,y+i,x+j]|
// x: [8,64,32,32] f32, W: [64,64,3,3] f32, out: [8,64,32,32] f32.
//
// INT16 SIMD core: quantize x,W to s16 (scale 2048), pack channel pairs
// {c, c+1} into one u32. vabsdiff2.s32.s32.s32.add does |d0|+|d1|+acc in ONE
// instruction, exact s32 accumulation (no promotes, no abs, no packs).
// Tiling: 256 CTAs (RT=4, FG=16), 512 thr, 2 CTAs/SM, 4 channel-quarters.

#define CIN   64
#define NFILT 64
#define HW    32
#define NIMG  8

#define FG    16
#define RT    4
#define XROWS (RT + 2)          // 6
#define XCOLS 34
#define NCP   (CIN / 2)         // 32 channel pairs

#define QSCALE 2048.0f
#define IQSCALE (1.0f / 2048.0f)

#define SX_U32 (NCP * XROWS * XCOLS)     // 6528 u32 = 26112 B
#define SW_U32 (NCP * 9 * FG)            // 4608 u32 = 18432 B
#define SMEM_BYTES ((SX_U32 + SW_U32) * 4)   // 44544 B ; sR (24KB) aliases sX

__device__ __forceinline__ int vad2(unsigned a, unsigned b, int c) {
    int d;
    asm("vabsdiff2.s32.s32.s32.add %0, %1, %2, %3;"
        : "=r"(d) : "r"(a), "r"(b), "r"(c));
    return d;
}

__device__ __forceinline__ unsigned q2(float a, float b) {
    int ia = __float2int_rn(a * QSCALE);
    int ib = __float2int_rn(b * QSCALE);
    ia = max(min(ia, 32767), -32767);
    ib = max(min(ib, 32767), -32767);
    return (unsigned)(ia & 0xFFFF) | ((unsigned)ib << 16);
}

__global__ __launch_bounds__(512, 2)
void adder2d_kernel(const float* __restrict__ x,
                    const float* __restrict__ W,
                    float* __restrict__ out)
{
    extern __shared__ unsigned smemu[];
    unsigned* sX = smemu;                  // [cp][r 0..5][col 0..33] {c,c+1} s16 pairs
    unsigned* sW = smemu + SX_U32;         // [cp][tap][f 0..15]     {c,c+1} s16 pairs
    int*      sR = (int*)smemu;            // aliases after main loop: [3][16][128]

    const int tid = threadIdx.x;
    const int qtr = tid >> 7;              // channel-pair quarter 0..3 (8 cpairs)
    const int wk  = tid & 127;             // worker = one output position
    const int yw  = wk >> 5;               // 0..3
    const int col = wk & 31;
    const int fg  = blockIdx.x;            // 0..3
    const int rt  = blockIdx.y;            // 0..7
    const int n   = blockIdx.z;            // 0..7
    const int y0  = rt * RT;
    const int f0  = fg * FG;

    // ---- quantize padded x slab into s16 channel-pairs ----
    const float* xn = x + (size_t)n * (CIN * HW * HW);
    for (int idx = tid; idx < SX_U32; idx += 512) {
        int cp  = idx / (XROWS * XCOLS);
        int rem = idx - cp * (XROWS * XCOLS);
        int r   = rem / XCOLS;
        int cc  = rem - r * XCOLS;
        int gr  = y0 - 1 + r;
        int gc  = cc - 1;
        float v0 = 0.0f, v1 = 0.0f;
        if ((unsigned)gr < HW && (unsigned)gc < HW) {
            v0 = xn[((2 * cp)     * HW + gr) * HW + gc];
            v1 = xn[((2 * cp + 1) * HW + gr) * HW + gc];
        }
        sX[idx] = q2(v0, v1);
    }
    // ---- quantize weights: sW[(cp*9+tap)*16 + f] = {W[f][2cp][tap], W[f][2cp+1][tap]} ----
    for (int idx = tid; idx < SW_U32; idx += 512) {
        int f   = idx & 15;
        int kt  = idx >> 4;                 // cp*9 + tap
        int cp  = kt / 9;
        int tap = kt - cp * 9;
        const float* wf = W + (size_t)(f0 + f) * (CIN * 9);
        sW[idx] = q2(wf[(2 * cp) * 9 + tap], wf[(2 * cp + 1) * 9 + tap]);
    }
    __syncthreads();

    int acc[16];
#pragma unroll
    for (int p = 0; p < 16; p++) acc[p] = 0;

    const unsigned* xrow = sX + (qtr * 8) * (XROWS * XCOLS) + yw * XCOLS + col;
    const unsigned* wch  = sW + (qtr * 8) * 9 * FG;

#pragma unroll 1
    for (int cp = 0; cp < 8; cp++) {        // 8 channel-pairs per quarter
#pragma unroll
        for (int i = 0; i < 3; i++) {
#pragma unroll
            for (int j = 0; j < 3; j++) {
                const unsigned xp = xrow[i * XCOLS + j];      // coalesced LDS.32
                const uint4 wA = *(const uint4*)(wch + (i * 3 + j) * FG);      // f 0..3
                const uint4 wB = *(const uint4*)(wch + (i * 3 + j) * FG + 4);  // f 4..7
                const uint4 wC = *(const uint4*)(wch + (i * 3 + j) * FG + 8);  // f 8..11
                const uint4 wD = *(const uint4*)(wch + (i * 3 + j) * FG + 12); // f 12..15
                acc[0]  = vad2(xp, wA.x, acc[0]);
                acc[1]  = vad2(xp, wA.y, acc[1]);
                acc[2]  = vad2(xp, wA.z, acc[2]);
                acc[3]  = vad2(xp, wA.w, acc[3]);
                acc[4]  = vad2(xp, wB.x, acc[4]);
                acc[5]  = vad2(xp, wB.y, acc[5]);
                acc[6]  = vad2(xp, wB.z, acc[6]);
                acc[7]  = vad2(xp, wB.w, acc[7]);
                acc[8]  = vad2(xp, wC.x, acc[8]);
                acc[9]  = vad2(xp, wC.y, acc[9]);
                acc[10] = vad2(xp, wC.z, acc[10]);
                acc[11] = vad2(xp, wC.w, acc[11]);
                acc[12] = vad2(xp, wD.x, acc[12]);
                acc[13] = vad2(xp, wD.y, acc[13]);
                acc[14] = vad2(xp, wD.z, acc[14]);
                acc[15] = vad2(xp, wD.w, acc[15]);
            }
        }
        xrow += XROWS * XCOLS;
        wch  += 9 * FG;
    }

    // ---- combine 4 quarters (sR aliases sX, now dead) ----
    __syncthreads();
    if (qtr != 0) {
        int* buf = sR + (size_t)(qtr - 1) * (16 * 128);
#pragma unroll
        for (int p = 0; p < 16; p++) buf[p * 128 + wk] = acc[p];   // conflict-free
    }
    __syncthreads();

    if (qtr == 0) {
#pragma unroll
        for (int p = 0; p < 16; p++) {
            int s = acc[p];
#pragma unroll
            for (int r = 0; r < 3; r++)
                s += sR[(size_t)r * (16 * 128) + p * 128 + wk];
            acc[p] = s;
        }
        // ---- write: out = -acc / 2048 ; filter = f0 + p ----
        const int gy = y0 + yw;
        float* outp = out + (((size_t)n * NFILT + f0) * HW + gy) * HW + col;
#pragma unroll
        for (int p = 0; p < 16; p++)
            outp[p * (HW * HW)] = (float)acc[p] * (-IQSCALE);
    }
}

extern "C" void kernel_launch(void* const* d_in, const int* in_sizes, int n_in,
                              void* d_out, int out_size)
{
    const float* x = (const float*)d_in[0];
    const float* W = (const float*)d_in[1];
    if (n_in >= 2 && in_sizes[0] == NFILT * CIN * 9 && in_sizes[1] == NIMG * CIN * HW * HW) {
        const float* t = x; x = W; W = t;
    }
    float* out = (float*)d_out;

    static int smem_set = -1;
    if (smem_set < 0) {
        cudaFuncSetAttribute(adder2d_kernel,
                             cudaFuncAttributeMaxDynamicSharedMemorySize, SMEM_BYTES);
        smem_set = 1;
    }

    dim3 grid(NFILT / FG, HW / RT, NIMG);   // 4 x 8 x 8 = 256 CTAs, 2 per SM
    adder2d_kernel<<<grid, 512, SMEM_BYTES>>>(x, W, out);
}

// round 13
// speedup vs baseline: 3.7277x; 3.7277x over previous
#include <cuda_runtime.h>
#include <cuda_fp16.h>

// AdderNet 2D (K=3,S=1,P=1): out[n,f,y,x] = -sum_{c,i,j} |W[f,c,i,j] - xpad[n,c,y+i,x+j]|
// x: [8,64,32,32] f32, W: [64,64,3,3] f32, out: [8,64,32,32] f32.
//
// fp16 HADD2 core (abs folded). 512 CTAs (RT=2), 256 thr, launch_bounds(256,2)
// -> 128-reg budget enables a REAL double-buffered weight pipeline: next
// i-row's 6x LDS.128 + 3x LDS.16 issued a full i-row (~51 instrs) before use.
// Parity fully unrolled (6 stages per channel-pair) -> no dynamic reg indexing.

#define CIN   64
#define NFILT 64
#define HW    32
#define NIMG  8

#define FG    16
#define RT    2
#define XROWS (RT + 2)          // 4
#define XCOLS 34

#define SX_ELEMS (CIN * XROWS * XCOLS)   // 8704 halves = 17408 B
#define SW_ELEMS (CIN * 9 * FG)          // 9216 halves = 18432 B
// +128 B pad: pipeline prefetch reads one row past the end (values unused)
#define SMEM_BYTES ((SX_ELEMS + SW_ELEMS) * 2 + 128)

__global__ __launch_bounds__(256, 2)
void adder2d_kernel(const float* __restrict__ x,
                    const float* __restrict__ W,
                    float* __restrict__ out)
{
    extern __shared__ __half smemh[];
    __half* sX = smemh;                       // [c][r 0..3][col 0..33] fp16, zero pad
    __half* sW = smemh + SX_ELEMS;            // [k=c*9+tap][ff 0..15]  fp16, NEGATED
    float*  sR = (float*)smemh;               // aliases after main loop: [3][16][64]

    const int tid = threadIdx.x;              // 0..255
    const int qtr = tid >> 6;                 // channel quarter 0..3 (16 ch each)
    const int wk  = tid & 63;                 // worker = one output position
    const int yw  = wk >> 5;                  // 0..1
    const int col = wk & 31;
    const int fg  = blockIdx.x;               // 0..3
    const int rt  = blockIdx.y;               // 0..15
    const int n   = blockIdx.z;               // 0..7
    const int y0  = rt * RT;
    const int f0  = fg * FG;

    // ---- load padded x slab, fp32 -> fp16 ----
    const float* xn = x + (size_t)n * (CIN * HW * HW);
    for (int idx = tid; idx < SX_ELEMS; idx += 256) {
        int c   = idx / (XROWS * XCOLS);
        int rem = idx - c * (XROWS * XCOLS);
        int r   = rem / XCOLS;
        int cc  = rem - r * XCOLS;
        int gr  = y0 - 1 + r;
        int gc  = cc - 1;
        float v = 0.0f;
        if ((unsigned)gr < HW && (unsigned)gc < HW)
            v = xn[(c * HW + gr) * HW + gc];
        sX[idx] = __float2half_rn(v);
    }
    // ---- NEGATED fp16 weights: sW[k*16 + ff] = -W[(f0+ff)*576 + k] ----
    for (int idx = tid; idx < SW_ELEMS; idx += 256) {
        int ff = idx / (CIN * 9);
        int k  = idx - ff * (CIN * 9);
        sW[k * FG + ff] = __float2half_rn(-W[(f0 + ff) * (CIN * 9) + k]);
    }
    __syncthreads();

    float facc[16];
#pragma unroll
    for (int p = 0; p < 16; p++) facc[p] = 0.0f;

    const int cbeg = qtr * 16;
    // running pointers; w rows of one i (3 taps x 16 filters = 48 halves) are
    // contiguous, so +48 walks (c,i) in order across channel boundaries too.
    const __half* xp = sX + cbeg * (XROWS * XCOLS) + yw * XCOLS + col;
    const __half* wp = sW + cbeg * 9 * FG;

    // ---- prologue: load stage 0 (c=cbeg, i=0) into buffer 0 ----
    uint4  wbuf0[6], wbuf1[6];
    __half xbuf0[3], xbuf1[3];
#pragma unroll
    for (int t = 0; t < 3; t++) {
        wbuf0[2 * t]     = *(const uint4*)(wp + t * FG);
        wbuf0[2 * t + 1] = *(const uint4*)(wp + t * FG + 8);
    }
#pragma unroll
    for (int j = 0; j < 3; j++) xbuf0[j] = xp[j];

#pragma unroll 1
    for (int cp = 0; cp < 8; cp++) {           // 8 channel-pairs (16 ch / quarter)
        __half2 hacc[8];
#pragma unroll
        for (int t = 0; t < 8; t++) hacc[t] = __float2half2_rn(0.0f);

#pragma unroll
        for (int s = 0; s < 6; s++) {          // 6 i-stages = 2 channels; parity s&1
            const int i = (s % 3);
            // next-stage pointers (contiguous w; x jumps to next channel after i=2)
            const __half* xpn = xp + ((i == 2) ? (XROWS * XCOLS - 2 * XCOLS) : XCOLS);
            const __half* wpn = wp + 3 * FG;

            if ((s & 1) == 0) {
                // prefetch next stage into buffer 1
#pragma unroll
                for (int t = 0; t < 3; t++) {
                    wbuf1[2 * t]     = *(const uint4*)(wpn + t * FG);
                    wbuf1[2 * t + 1] = *(const uint4*)(wpn + t * FG + 8);
                }
#pragma unroll
                for (int j = 0; j < 3; j++) xbuf1[j] = xpn[j];
                // compute with buffer 0
#pragma unroll
                for (int j = 0; j < 3; j++) {
                    __half2 xj = __half2half2(xbuf0[j]);
                    const __half2* wa = (const __half2*)&wbuf0[2 * j];
                    const __half2* wb = (const __half2*)&wbuf0[2 * j + 1];
#pragma unroll
                    for (int q = 0; q < 4; q++) {
                        __half2 d;
                        d = __hadd2(xj, wa[q]); hacc[q]     = __hadd2(hacc[q],     __habs2(d));
                        d = __hadd2(xj, wb[q]); hacc[4 + q] = __hadd2(hacc[4 + q], __habs2(d));
                    }
                }
            } else {
                // prefetch next stage into buffer 0
#pragma unroll
                for (int t = 0; t < 3; t++) {
                    wbuf0[2 * t]     = *(const uint4*)(wpn + t * FG);
                    wbuf0[2 * t + 1] = *(const uint4*)(wpn + t * FG + 8);
                }
#pragma unroll
                for (int j = 0; j < 3; j++) xbuf0[j] = xpn[j];
                // compute with buffer 1
#pragma unroll
                for (int j = 0; j < 3; j++) {
                    __half2 xj = __half2half2(xbuf1[j]);
                    const __half2* wa = (const __half2*)&wbuf1[2 * j];
                    const __half2* wb = (const __half2*)&wbuf1[2 * j + 1];
#pragma unroll
                    for (int q = 0; q < 4; q++) {
                        __half2 d;
                        d = __hadd2(xj, wa[q]); hacc[q]     = __hadd2(hacc[q],     __habs2(d));
                        d = __hadd2(xj, wb[q]); hacc[4 + q] = __hadd2(hacc[4 + q], __habs2(d));
                    }
                }
            }
            xp = xpn;
            wp = wpn;
        }
        // ---- promote fp16 partials (18 taps) into fp32 ----
#pragma unroll
        for (int t = 0; t < 8; t++) {
            float2 f = __half22float2(hacc[t]);
            facc[2 * t]     += f.x;
            facc[2 * t + 1] += f.y;
        }
    }

    // ---- combine 4 channel quarters (sR aliases sX, now dead) ----
    __syncthreads();
    if (qtr != 0) {
        float* buf = sR + (size_t)(qtr - 1) * (16 * 64);
#pragma unroll
        for (int p = 0; p < 16; p++) buf[p * 64 + wk] = facc[p];   // conflict-free
    }
    __syncthreads();

    if (qtr == 0) {
#pragma unroll
        for (int p = 0; p < 16; p++) {
            float s = facc[p];
#pragma unroll
            for (int r = 0; r < 3; r++)
                s += sR[(size_t)r * (16 * 64) + p * 64 + wk];
            facc[p] = s;
        }
        // ---- write: t = g*4 + q ; filter = g*8 + 2q + lane ----
        const int gy = y0 + yw;
#pragma unroll
        for (int t = 0; t < 8; t++) {
            int g = t >> 2;
            int q = t & 3;
            int f = g * 8 + q * 2;
            float* outp = out + (((size_t)n * NFILT + f0 + f) * HW + gy) * HW + col;
            outp[0]       = -facc[2 * t];
            outp[HW * HW] = -facc[2 * t + 1];
        }
    }
}

extern "C" void kernel_launch(void* const* d_in, const int* in_sizes, int n_in,
                              void* d_out, int out_size)
{
    const float* x = (const float*)d_in[0];
    const float* W = (const float*)d_in[1];
    if (n_in >= 2 && in_sizes[0] == NFILT * CIN * 9 && in_sizes[1] == NIMG * CIN * HW * HW) {
        const float* t = x; x = W; W = t;
    }
    float* out = (float*)d_out;

    static int smem_set = -1;
    if (smem_set < 0) {
        cudaFuncSetAttribute(adder2d_kernel,
                             cudaFuncAttributeMaxDynamicSharedMemorySize, SMEM_BYTES);
        smem_set = 1;
    }

    dim3 grid(NFILT / FG, HW / RT, NIMG);   // 4 x 16 x 8 = 512 CTAs, 2 resident/SM
    adder2d_kernel<<<grid, 256, SMEM_BYTES>>>(x, W, out);
}

// round 14
// speedup vs baseline: 4.1192x; 1.1050x over previous
#include <cuda_runtime.h>
#include <cuda_fp16.h>

// AdderNet 2D (K=3,S=1,P=1): out[n,f,y,x] = -sum_{c,i,j} |W[f,c,i,j] - xpad[n,c,y+i,x+j]|
// x: [8,64,32,32] f32, W: [64,64,3,3] f32, out: [8,64,32,32] f32.
//
// Two-phase: prep kernel quantizes x -> padded fp16 [n][c][34][34] and W ->
// negated/transposed fp16 [fg][k=c*9+tap][f 0..15] in device globals. Main
// kernel (R7 core, best so far) then has a trivial copy prologue.

#define CIN   64
#define NFILT 64
#define HW    32
#define NIMG  8

#define FG    16
#define RT    4
#define XROWS (RT + 2)          // 6
#define XCOLS 34
#define PHW   34                // padded H/W in g_qX

#define SX_ELEMS (CIN * XROWS * XCOLS)   // 13056 halves = 26112 B
#define SW_ELEMS (CIN * 9 * FG)          // 9216 halves  = 18432 B
#define SMEM_BYTES ((SX_ELEMS + SW_ELEMS) * 2)   // 44544 B ; sR (24KB) aliases sX

#define QX_ELEMS (NIMG * CIN * PHW * PHW)  // 591872
#define QW_ELEMS (4 * CIN * 9 * FG)        // 36864
#define PREP_TOTAL (QX_ELEMS + QW_ELEMS)

__device__ __half g_qX[QX_ELEMS];          // [n][c][ph][pw], zero border
__device__ __half g_qW[QW_ELEMS];          // [fg][k][f], NEGATED

__global__ __launch_bounds__(256, 8)
void prep_kernel(const float* __restrict__ x, const float* __restrict__ W)
{
    int idx = blockIdx.x * 256 + threadIdx.x;
    if (idx < QX_ELEMS) {
        int pw = idx % PHW;
        int t  = idx / PHW;
        int ph = t % PHW;
        int nc = t / PHW;
        float v = 0.0f;
        if (ph >= 1 && ph < 33 && pw >= 1 && pw < 33)
            v = x[(size_t)nc * (HW * HW) + (ph - 1) * HW + (pw - 1)];
        g_qX[idx] = __float2half_rn(v);
    } else if (idx < PREP_TOTAL) {
        int wi = idx - QX_ELEMS;
        int f  = wi & 15;
        int k  = (wi >> 4) % (CIN * 9);
        int fg = wi / (16 * CIN * 9);
        g_qW[wi] = __float2half_rn(-W[(size_t)(fg * FG + f) * (CIN * 9) + k]);
    }
}

__global__ __launch_bounds__(512, 2)
void adder2d_kernel(float* __restrict__ out)
{
    extern __shared__ __half smemh[];
    __half* sX = smemh;                       // [c][r 0..5][col 0..33] fp16
    __half* sW = smemh + SX_ELEMS;            // [k][ff 0..15] fp16, NEGATED
    float*  sR = (float*)smemh;               // aliases after main loop: [3][16][128]

    const int tid = threadIdx.x;
    const int qtr = tid >> 7;                 // channel quarter 0..3
    const int wk  = tid & 127;                // worker = one output position
    const int yw  = wk >> 5;                  // 0..3
    const int col = wk & 31;
    const int fg  = blockIdx.x;               // 0..3
    const int rt  = blockIdx.y;               // 0..7
    const int n   = blockIdx.z;               // 0..7
    const int y0  = rt * RT;
    const int f0  = fg * FG;

    // ---- x slab: straight uint copies from padded g_qX (rows contiguous) ----
    {
        const unsigned* srcx = (const unsigned*)g_qX
                             + (size_t)n * CIN * (PHW * PHW / 2) + y0 * (PHW / 2);
        unsigned* dstx = (unsigned*)sX;
        for (int idx = tid; idx < CIN * (XROWS * XCOLS / 2); idx += 512) {
            int c   = idx / (XROWS * XCOLS / 2);          // /102
            int off = idx - c * (XROWS * XCOLS / 2);
            dstx[idx] = srcx[c * (PHW * PHW / 2) + off];
        }
    }
    // ---- weight tile: pure uint4 memcpy ----
    {
        const uint4* srcw = (const uint4*)(g_qW + fg * SW_ELEMS);
        uint4* dstw = (uint4*)sW;
        for (int idx = tid; idx < SW_ELEMS / 8; idx += 512)
            dstw[idx] = srcw[idx];
    }
    __syncthreads();

    float facc[16];
#pragma unroll
    for (int p = 0; p < 16; p++) facc[p] = 0.0f;

    const int cbeg = qtr * (CIN / 4);
    const __half* xrow = sX + cbeg * (XROWS * XCOLS) + yw * XCOLS + col;
    const __half* wch  = sW + cbeg * 9 * FG;

#pragma unroll 1
    for (int cp = 0; cp < CIN / 8; cp++) {     // 8 pairs of channels
        __half2 hacc[8];
#pragma unroll
        for (int t = 0; t < 8; t++) hacc[t] = __float2half2_rn(0.0f);

#pragma unroll
        for (int cc = 0; cc < 2; cc++) {       // 2 channels per promote (18 taps)
#pragma unroll
            for (int i = 0; i < 3; i++) {
                __half2 xa[3];
#pragma unroll
                for (int j = 0; j < 3; j++)
                    xa[j] = __half2half2(xrow[i * XCOLS + j]);
#pragma unroll
                for (int j = 0; j < 3; j++) {
                    const uint4 rA = *(const uint4*)(wch + (i * 3 + j) * FG);     // f 0..7
                    const uint4 rB = *(const uint4*)(wch + (i * 3 + j) * FG + 8); // f 8..15
                    const __half2* wa = (const __half2*)&rA;
                    const __half2* wb = (const __half2*)&rB;
#pragma unroll
                    for (int q = 0; q < 4; q++) {
                        __half2 d;
                        d = __hadd2(xa[j], wa[q]); hacc[q]     = __hadd2(hacc[q],     __habs2(d));
                        d = __hadd2(xa[j], wb[q]); hacc[4 + q] = __hadd2(hacc[4 + q], __habs2(d));
                    }
                }
            }
            xrow += XROWS * XCOLS;
            wch  += 9 * FG;
        }
#pragma unroll
        for (int t = 0; t < 8; t++) {
            float2 f = __half22float2(hacc[t]);
            facc[2 * t]     += f.x;
            facc[2 * t + 1] += f.y;
        }
    }

    // ---- combine 4 channel quarters (sR aliases sX, now dead) ----
    __syncthreads();
    if (qtr != 0) {
        float* buf = sR + (size_t)(qtr - 1) * (16 * 128);
#pragma unroll
        for (int p = 0; p < 16; p++) buf[p * 128 + wk] = facc[p];  // conflict-free
    }
    __syncthreads();

    if (qtr == 0) {
#pragma unroll
        for (int p = 0; p < 16; p++) {
            float s = facc[p];
#pragma unroll
            for (int r = 0; r < 3; r++)
                s += sR[(size_t)r * (16 * 128) + p * 128 + wk];
            facc[p] = s;
        }
        // ---- write: t = g*4 + q ; filter = g*8 + 2q + lane ----
        const int gy = y0 + yw;
#pragma unroll
        for (int t = 0; t < 8; t++) {
            int g = t >> 2;
            int q = t & 3;
            int f = g * 8 + q * 2;
            float* outp = out + (((size_t)n * NFILT + f0 + f) * HW + gy) * HW + col;
            outp[0]       = -facc[2 * t];
            outp[HW * HW] = -facc[2 * t + 1];
        }
    }
}

extern "C" void kernel_launch(void* const* d_in, const int* in_sizes, int n_in,
                              void* d_out, int out_size)
{
    const float* x = (const float*)d_in[0];
    const float* W = (const float*)d_in[1];
    if (n_in >= 2 && in_sizes[0] == NFILT * CIN * 9 && in_sizes[1] == NIMG * CIN * HW * HW) {
        const float* t = x; x = W; W = t;
    }
    float* out = (float*)d_out;

    static int smem_set = -1;
    if (smem_set < 0) {
        cudaFuncSetAttribute(adder2d_kernel,
                             cudaFuncAttributeMaxDynamicSharedMemorySize, SMEM_BYTES);
        smem_set = 1;
    }

    prep_kernel<<<(PREP_TOTAL + 255) / 256, 256>>>(x, W);

    dim3 grid(NFILT / FG, HW / RT, NIMG);   // 4 x 8 x 8 = 256 CTAs, 2 per SM
    adder2d_kernel<<<grid, 512, SMEM_BYTES>>>(out);
}